// round 13
// baseline (speedup 1.0000x reference)
#include <cuda_runtime.h>
#include <cuda_bf16.h>
#include <cstdint>
#include <math.h>

#define Bv 8
#define Fv 4
#define Tv 1024
#define Sv 1024
#define Cv 32
#define C2v 64
#define NHv 2
#define HDv 16
#define NSPLIT 4

// Scratch (device globals: no allocation allowed)
__device__ float g_q[Bv*Fv*Tv*Cv];    // 4 MB
__device__ float g_k[Bv*Sv*Cv];       // 1 MB
__device__ float g_v[Bv*Sv*Cv];       // 1 MB
__device__ float g_y0[Bv*Fv*Tv*Cv];   // 4 MB  (split partials, unnormalized)
__device__ float g_y1[Bv*Fv*Tv*Cv];
__device__ float g_y2[Bv*Fv*Tv*Cv];
__device__ float g_y3[Bv*Fv*Tv*Cv];
__device__ float g_l[NSPLIT*Bv*NHv*Fv*Tv];  // 1 MB (partial row sums)

__device__ __forceinline__ float gelu_f(float x) {
    return 0.5f * x * (1.0f + erff(x * 0.7071067811865476f));
}

// tanh-approx gelu (HW tanh.approx)
__device__ __forceinline__ float gelu_t(float x) {
    float u = 0.7978845608028654f * x * (1.0f + 0.044715f * x * x);
    float t;
    asm("tanh.approx.f32 %0, %1;" : "=f"(t) : "f"(u));
    return 0.5f * x * (1.0f + t);
}

// Guaranteed-MUFU exp2 (exp2f is only MUFU under fast-math; this always is).
__device__ __forceinline__ float ex2_approx(float x) {
    float y;
    asm("ex2.approx.f32 %0, %1;" : "=f"(y) : "f"(x));
    return y;
}

__device__ __forceinline__ uint32_t f2tf32(float f) {
    uint32_t u;
    asm("cvt.rna.tf32.f32 %0, %1;" : "=r"(u) : "f"(f));
    return u;
}

__device__ __forceinline__ uint32_t pack_bf16x2(float lo, float hi) {
    __nv_bfloat162 p = __floats2bfloat162_rn(lo, hi);   // x=lo, y=hi
    return *reinterpret_cast<uint32_t*>(&p);
}

__device__ __forceinline__ void mma_tf32(float c[4], const uint32_t a[4], const uint32_t b[2]) {
    asm volatile(
        "mma.sync.aligned.m16n8k8.row.col.f32.tf32.tf32.f32 "
        "{%0,%1,%2,%3},{%4,%5,%6,%7},{%8,%9},{%0,%1,%2,%3};"
        : "+f"(c[0]), "+f"(c[1]), "+f"(c[2]), "+f"(c[3])
        : "r"(a[0]), "r"(a[1]), "r"(a[2]), "r"(a[3]), "r"(b[0]), "r"(b[1]));
}

__device__ __forceinline__ void mma_bf16(float c[4], const uint32_t a[4], const uint32_t b[2]) {
    asm volatile(
        "mma.sync.aligned.m16n8k16.row.col.f32.bf16.bf16.f32 "
        "{%0,%1,%2,%3},{%4,%5,%6,%7},{%8,%9},{%0,%1,%2,%3};"
        : "+f"(c[0]), "+f"(c[1]), "+f"(c[2]), "+f"(c[3])
        : "r"(a[0]), "r"(a[1]), "r"(a[2]), "r"(a[3]), "r"(b[0]), "r"(b[1]));
}

// ---------------------------------------------------------------------------
// TCL v2 (unchanged from round 10 — 19.5us, validated)
// ---------------------------------------------------------------------------
#define XSTR 52

__global__ __launch_bounds__(128) void tcl_mma_kernel(
    const float* __restrict__ causal, const float* __restrict__ pastkv,
    float* __restrict__ qo, float* __restrict__ ko, float* __restrict__ vo,
    const float* __restrict__ wqc, const float* __restrict__ bqc,
    const float* __restrict__ wqp, const float* __restrict__ bqp,
    const float* __restrict__ wkc, const float* __restrict__ bkc,
    const float* __restrict__ wkp, const float* __restrict__ bkp,
    const float* __restrict__ wvc, const float* __restrict__ bvc,
    const float* __restrict__ wvp, const float* __restrict__ bvp)
{
    __shared__ uint32_t Xp[128*XSTR];
    __shared__ uint32_t Wcp[64*XSTR];
    __shared__ uint32_t Wpp[32*XSTR];
    __shared__ float bcs[C2v];
    __shared__ float bps[Cv];

    const int bid = blockIdx.x;
    const int stream = bid >> 3, tile = bid & 7;
    const float *x, *wconv, *bconv, *wproj, *bproj;
    float* out;
    if (stream < 32) {
        x = causal + (long)stream*32768; out = qo + (long)stream*32768;
        wconv = wqc; bconv = bqc; wproj = wqp; bproj = bqp;
    } else if (stream < 40) {
        int n = stream - 32;
        x = pastkv + (long)n*32768; out = ko + (long)n*32768;
        wconv = wkc; bconv = bkc; wproj = wkp; bproj = bkp;
    } else {
        int n = stream - 40;
        x = pastkv + (long)n*32768; out = vo + (long)n*32768;
        wconv = wvc; bconv = bvc; wproj = wvp; bproj = bvp;
    }

    const int tid = threadIdx.x;
    const int t0 = tile * 128;

    for (int i = tid; i < 64*48; i += 128) {
        int n = i / 48, kp = i % 48;
        int tap = kp >> 4, c = (kp & 15) * 2;
        Wcp[n*XSTR + kp] = pack_bf16x2(wconv[(n*Cv + c)*3 + tap],
                                       wconv[(n*Cv + c+1)*3 + tap]);
    }
    for (int i = tid; i < 32*32; i += 128) {
        int n = i >> 5, kp = i & 31;
        Wpp[n*XSTR + kp] = pack_bf16x2(wproj[n*C2v + 2*kp], wproj[n*C2v + 2*kp+1]);
    }
    if (tid < C2v) bcs[tid] = bconv[tid];
    if (tid < Cv)  bps[tid] = bproj[tid];

    for (int i = tid; i < 128*48; i += 128) {
        int r = i / 48, kp = i % 48;
        int tap = kp >> 4, c = (kp & 15) * 2;
        int t = t0 + r - 2 + tap;
        uint32_t val = 0u;
        if (t >= 0) {
            const float* src = x + (long)t*Cv + c;
            val = pack_bf16x2(src[0], src[1]);
        }
        Xp[r*XSTR + kp] = val;
    }
    __syncthreads();

    const int w  = tid >> 5, l = tid & 31;
    const int lq = l >> 2, lr = l & 3;
    const int r0 = w * 32;

    float Cc[2][8][4];
    #pragma unroll
    for (int mt = 0; mt < 2; mt++)
        #pragma unroll
        for (int nt = 0; nt < 8; nt++)
            #pragma unroll
            for (int e = 0; e < 4; e++) Cc[mt][nt][e] = 0.f;

    #pragma unroll
    for (int ks = 0; ks < 6; ks++) {
        uint32_t a[2][4];
        #pragma unroll
        for (int mt = 0; mt < 2; mt++) {
            int rr = r0 + mt*16;
            a[mt][0] = Xp[(rr+lq)*XSTR   + ks*8 + lr];
            a[mt][1] = Xp[(rr+lq+8)*XSTR + ks*8 + lr];
            a[mt][2] = Xp[(rr+lq)*XSTR   + ks*8 + lr + 4];
            a[mt][3] = Xp[(rr+lq+8)*XSTR + ks*8 + lr + 4];
        }
        #pragma unroll
        for (int nt = 0; nt < 8; nt++) {
            uint32_t bf[2];
            bf[0] = Wcp[(nt*8+lq)*XSTR + ks*8 + lr];
            bf[1] = Wcp[(nt*8+lq)*XSTR + ks*8 + lr + 4];
            mma_bf16(Cc[0][nt], a[0], bf);
            mma_bf16(Cc[1][nt], a[1], bf);
        }
    }

    uint32_t pa[2][4][4];
    #pragma unroll
    for (int ks2 = 0; ks2 < 4; ks2++) {
        float b0 = bcs[(2*ks2)*8   + 2*lr], b1 = bcs[(2*ks2)*8   + 2*lr + 1];
        float b2 = bcs[(2*ks2+1)*8 + 2*lr], b3 = bcs[(2*ks2+1)*8 + 2*lr + 1];
        #pragma unroll
        for (int mt = 0; mt < 2; mt++) {
            pa[mt][ks2][0] = pack_bf16x2(gelu_t(Cc[mt][2*ks2][0]+b0),   gelu_t(Cc[mt][2*ks2][1]+b1));
            pa[mt][ks2][1] = pack_bf16x2(gelu_t(Cc[mt][2*ks2][2]+b0),   gelu_t(Cc[mt][2*ks2][3]+b1));
            pa[mt][ks2][2] = pack_bf16x2(gelu_t(Cc[mt][2*ks2+1][0]+b2), gelu_t(Cc[mt][2*ks2+1][1]+b3));
            pa[mt][ks2][3] = pack_bf16x2(gelu_t(Cc[mt][2*ks2+1][2]+b2), gelu_t(Cc[mt][2*ks2+1][3]+b3));
        }
    }

    float Cp[2][4][4];
    #pragma unroll
    for (int mt = 0; mt < 2; mt++)
        #pragma unroll
        for (int nt = 0; nt < 4; nt++)
            #pragma unroll
            for (int e = 0; e < 4; e++) Cp[mt][nt][e] = 0.f;

    #pragma unroll
    for (int ks2 = 0; ks2 < 4; ks2++) {
        #pragma unroll
        for (int nt = 0; nt < 4; nt++) {
            uint32_t bf[2];
            bf[0] = Wpp[(nt*8+lq)*XSTR + ks2*8 + lr];
            bf[1] = Wpp[(nt*8+lq)*XSTR + ks2*8 + lr + 4];
            mma_bf16(Cp[0][nt], pa[0][ks2], bf);
            mma_bf16(Cp[1][nt], pa[1][ks2], bf);
        }
    }

    #pragma unroll
    for (int mt = 0; mt < 2; mt++) {
        #pragma unroll
        for (int nt = 0; nt < 4; nt++) {
            int col = nt*8 + 2*lr;
            float bo0 = bps[col], bo1 = bps[col+1];
            long row = t0 + r0 + mt*16 + lq;
            *(float2*)(out + row*Cv + col)     = make_float2(Cp[mt][nt][0]+bo0, Cp[mt][nt][1]+bo1);
            *(float2*)(out + (row+8)*Cv + col) = make_float2(Cp[mt][nt][2]+bo0, Cp[mt][nt][3]+bo1);
        }
    }
}

// ---------------------------------------------------------------------------
// Attention v5.1: identical to round 11 except exp2 via guaranteed-MUFU asm.
// ---------------------------------------------------------------------------
#define CH 256         // s range per block (= Sv/NSPLIT), staged once
#define KSTR 20        // Ks row stride (floats)
#define VSTR 24        // Vp pair-row stride (u32)
#define QSCALE 0.3606737602222409f   // 0.25 * log2(e)

__global__ __launch_bounds__(256) void attn_mma_kernel(
    const float* __restrict__ q, const float* __restrict__ k,
    const float* __restrict__ v,
    float* __restrict__ y0, float* __restrict__ y1,
    float* __restrict__ y2, float* __restrict__ y3,
    float* __restrict__ lpart)
{
    __shared__ float    Ks[CH*KSTR];        // 20 KB
    __shared__ uint32_t Vp[(CH/2)*VSTR];    // 12 KB

    const int tid = threadIdx.x;
    const int w   = tid >> 5;
    const int l   = tid & 31;
    const int lq  = l >> 2;
    const int lr  = l & 3;
    const int b     = blockIdx.z;
    const int h     = blockIdx.y >> 2;
    const int split = blockIdx.y & 3;

    const int rowbase = blockIdx.x * 256 + w * 32;
    const int f  = rowbase >> 10;
    const int t0 = rowbase & 1023;
    const float* qbase = q + (((long)(b*Fv + f))*Tv + t0)*Cv + h*HDv;

    // Q fragments, prescaled by 0.25*log2(e) -> scores in log2 domain
    uint32_t qa[2][2][4];
    #pragma unroll
    for (int mt = 0; mt < 2; mt++)
        #pragma unroll
        for (int ks = 0; ks < 2; ks++) {
            int r0 = mt*16 + lq;
            int c0 = ks*8 + lr;
            qa[mt][ks][0] = f2tf32(qbase[(long)r0*Cv + c0]       * QSCALE);
            qa[mt][ks][1] = f2tf32(qbase[(long)(r0+8)*Cv + c0]   * QSCALE);
            qa[mt][ks][2] = f2tf32(qbase[(long)r0*Cv + c0+4]     * QSCALE);
            qa[mt][ks][3] = f2tf32(qbase[(long)(r0+8)*Cv + c0+4] * QSCALE);
        }

    float O[2][2][4];
    #pragma unroll
    for (int i = 0; i < 2; i++)
        #pragma unroll
        for (int j = 0; j < 2; j++)
            #pragma unroll
            for (int e = 0; e < 4; e++) O[i][j][e] = 0.f;
    float ls[4] = {0.f, 0.f, 0.f, 0.f};

    const int s0 = split * CH;
    const float* kb = k + ((long)b*Sv + s0)*Cv + h*HDv;
    const float* vb = v + ((long)b*Sv + s0)*Cv + h*HDv;

    // Stage once (no loop; SMEM read-only afterwards)
    for (int i = tid; i < CH*16; i += 256) {
        int s = i >> 4, d = i & 15;
        Ks[s*KSTR + d] = __uint_as_float(f2tf32(kb[(long)s*Cv + d]));
    }
    for (int i = tid; i < (CH/2)*16; i += 256) {
        int s2 = i >> 4, d = i & 15;
        Vp[s2*VSTR + d] = pack_bf16x2(vb[(long)(2*s2)*Cv + d],
                                      vb[(long)(2*s2+1)*Cv + d]);
    }
    __syncthreads();

    #pragma unroll 4
    for (int ntp = 0; ntp < CH/16; ntp++) {     // 16-s slices
        uint32_t pa[2][4];
        #pragma unroll
        for (int half = 0; half < 2; half++) {
            int snt = ntp*16 + half*8;
            uint32_t kf[2][2];
            #pragma unroll
            for (int ks = 0; ks < 2; ks++) {
                int dbase = ks*8 + lr;
                kf[ks][0] = __float_as_uint(Ks[(snt + lq)*KSTR + dbase]);
                kf[ks][1] = __float_as_uint(Ks[(snt + lq)*KSTR + dbase + 4]);
            }
            #pragma unroll
            for (int mt = 0; mt < 2; mt++) {
                float c[4] = {0.f, 0.f, 0.f, 0.f};
                mma_tf32(c, qa[mt][0], kf[0]);
                mma_tf32(c, qa[mt][1], kf[1]);
                float e0 = ex2_approx(fminf(c[0], 115.f));
                float e1 = ex2_approx(fminf(c[1], 115.f));
                float e2 = ex2_approx(fminf(c[2], 115.f));
                float e3 = ex2_approx(fminf(c[3], 115.f));
                ls[mt*2]   += e0 + e1;
                ls[mt*2+1] += e2 + e3;
                pa[mt][half*2 + 0] = pack_bf16x2(e0, e1);
                pa[mt][half*2 + 1] = pack_bf16x2(e2, e3);
            }
        }
        int s2base = ntp * 8;
        #pragma unroll
        for (int dn = 0; dn < 2; dn++) {
            uint32_t vf[2];
            vf[0] = Vp[(s2base + lr)*VSTR + dn*8 + lq];
            vf[1] = Vp[(s2base + lr + 4)*VSTR + dn*8 + lq];
            mma_bf16(O[0][dn], pa[0], vf);
            mma_bf16(O[1][dn], pa[1], vf);
        }
    }

    #pragma unroll
    for (int i = 0; i < 4; i++) {
        ls[i] += __shfl_xor_sync(0xffffffffu, ls[i], 1);
        ls[i] += __shfl_xor_sync(0xffffffffu, ls[i], 2);
    }

    float* ybuf = (split == 0) ? y0 : (split == 1) ? y1 : (split == 2) ? y2 : y3;
    float* yout = ybuf + (((long)(b*Fv + f))*Tv + t0)*Cv + h*HDv;
    #pragma unroll
    for (int mt = 0; mt < 2; mt++)
        #pragma unroll
        for (int dn = 0; dn < 2; dn++) {
            int d0 = dn*8 + 2*lr;
            int r0 = mt*16 + lq;
            *(float2*)(yout + (long)r0*Cv + d0)     = make_float2(O[mt][dn][0], O[mt][dn][1]);
            *(float2*)(yout + (long)(r0+8)*Cv + d0) = make_float2(O[mt][dn][2], O[mt][dn][3]);
        }

    if (lr == 0) {
        long lb = ((long)(split*Bv + b)*NHv + h)*(Fv*Tv) + rowbase;
        #pragma unroll
        for (int mt = 0; mt < 2; mt++) {
            lpart[lb + mt*16 + lq]     = ls[mt*2];
            lpart[lb + mt*16 + lq + 8] = ls[mt*2+1];
        }
    }
}

// ---------------------------------------------------------------------------
// Epilogue (unchanged from round 11)
// ---------------------------------------------------------------------------
__global__ void epi_kernel(const float* __restrict__ causal,
                           const float* __restrict__ y0, const float* __restrict__ y1,
                           const float* __restrict__ y2, const float* __restrict__ y3,
                           const float* __restrict__ lpart,
                           const float* __restrict__ wc, const float* __restrict__ lnw,
                           const float* __restrict__ wfc, const float* __restrict__ wmp,
                           float* __restrict__ out)
{
    __shared__ float wcs[32*32];
    __shared__ float wfcs[32*32];
    __shared__ float wmps[32*32];
    __shared__ float lns[32];
    __shared__ float stage[8][32];

    int tid = threadIdx.x;
    for (int i = tid; i < 1024; i += 256) {
        int a = i >> 5, bcol = i & 31;
        wcs[i]  = wc[bcol*32 + a];
        wfcs[i] = wfc[bcol*32 + a];
        wmps[i] = wmp[bcol*32 + a];
    }
    if (tid < 32) lns[tid] = lnw[tid];
    __syncthreads();

    int wid = tid >> 5, lane = tid & 31;
    long row = (long)blockIdx.x * 8 + wid;
    int b  = (int)(row >> 12);
    int ft = (int)(row & 4095);
    int h  = lane >> 4;

    const long LSTRIDE = (long)Bv*NHv*Fv*Tv;
    long lidx = ((long)b*NHv + h)*(Fv*Tv) + ft;
    float lsum = lpart[lidx] + lpart[LSTRIDE + lidx]
               + lpart[2*LSTRIDE + lidx] + lpart[3*LSTRIDE + lidx];
    float yc = (y0[row*32 + lane] + y1[row*32 + lane]
              + y2[row*32 + lane] + y3[row*32 + lane]) / lsum;
    stage[wid][lane] = yc;
    __syncwarp();

    float o = causal[row*32 + lane];
    #pragma unroll
    for (int j = 0; j < 32; j++) o += stage[wid][j] * wcs[j*32 + lane];
    __syncwarp();

    float sum = o, sq = o*o;
    #pragma unroll
    for (int off = 16; off; off >>= 1) {
        sum += __shfl_xor_sync(0xffffffffu, sum, off);
        sq  += __shfl_xor_sync(0xffffffffu, sq, off);
    }
    float mu  = sum * (1.0f/32.0f);
    float var = sq  * (1.0f/32.0f) - mu*mu;
    float hn = (o - mu) * rsqrtf(var + 1e-5f) * lns[lane];

    stage[wid][lane] = hn;
    __syncwarp();
    float g = 0.f;
    #pragma unroll
    for (int j = 0; j < 32; j++) g += stage[wid][j] * wfcs[j*32 + lane];
    __syncwarp();
    g = gelu_f(g);
    stage[wid][lane] = g;
    __syncwarp();
    float mlp = 0.f;
    #pragma unroll
    for (int j = 0; j < 32; j++) mlp += stage[wid][j] * wmps[j*32 + lane];

    out[row*32 + lane] = o + mlp;
}

// ---------------------------------------------------------------------------
extern "C" void kernel_launch(void* const* d_in, const int* in_sizes, int n_in,
                              void* d_out, int out_size)
{
    const float* causal  = (const float*)d_in[0];
    const float* pastkv  = (const float*)d_in[1];
    const float* wq_conv = (const float*)d_in[2];
    const float* bq_conv = (const float*)d_in[3];
    const float* wq_proj = (const float*)d_in[4];
    const float* bq_proj = (const float*)d_in[5];
    const float* wk_conv = (const float*)d_in[6];
    const float* bk_conv = (const float*)d_in[7];
    const float* wk_proj = (const float*)d_in[8];
    const float* bk_proj = (const float*)d_in[9];
    const float* wv_conv = (const float*)d_in[10];
    const float* bv_conv = (const float*)d_in[11];
    const float* wv_proj = (const float*)d_in[12];
    const float* bv_proj = (const float*)d_in[13];
    const float* w_cproj = (const float*)d_in[14];
    const float* ln_w    = (const float*)d_in[15];
    const float* w_fc    = (const float*)d_in[16];
    const float* w_mlp   = (const float*)d_in[17];
    float* out = (float*)d_out;

    float *q, *k, *v, *y0, *y1, *y2, *y3, *lp;
    cudaGetSymbolAddress((void**)&q,  g_q);
    cudaGetSymbolAddress((void**)&k,  g_k);
    cudaGetSymbolAddress((void**)&v,  g_v);
    cudaGetSymbolAddress((void**)&y0, g_y0);
    cudaGetSymbolAddress((void**)&y1, g_y1);
    cudaGetSymbolAddress((void**)&y2, g_y2);
    cudaGetSymbolAddress((void**)&y3, g_y3);
    cudaGetSymbolAddress((void**)&lp, g_l);

    tcl_mma_kernel<<<384, 128>>>(causal, pastkv, q, k, v,
                                 wq_conv, bq_conv, wq_proj, bq_proj,
                                 wk_conv, bk_conv, wk_proj, bk_proj,
                                 wv_conv, bv_conv, wv_proj, bv_proj);

    // 256-row q tiles, S split in 4: grid (16, NHv*NSPLIT, Bv) = 1024 blocks
    attn_mma_kernel<<<dim3((Fv*Tv)/256, NHv*NSPLIT, Bv), 256>>>(q, k, v, y0, y1, y2, y3, lp);

    epi_kernel<<<(Bv*Fv*Tv)/8, 256>>>(causal, y0, y1, y2, y3, lp,
                                      w_cproj, ln_w, w_fc, w_mlp, out);
}

// round 17
// speedup vs baseline: 1.3355x; 1.3355x over previous
#include <cuda_runtime.h>
#include <cuda_bf16.h>
#include <cstdint>
#include <math.h>

#define Bv 8
#define Fv 4
#define Tv 1024
#define Sv 1024
#define Cv 32
#define C2v 64
#define NHv 2
#define HDv 16
#define NSPLIT 4

// Scratch (device globals: no allocation allowed)
__device__ float g_q[Bv*Fv*Tv*Cv];    // 4 MB
__device__ float g_k[Bv*Sv*Cv];       // 1 MB
__device__ float g_v[Bv*Sv*Cv];       // 1 MB
__device__ float g_y0[Bv*Fv*Tv*Cv];   // 4 MB  (split partials, unnormalized)
__device__ float g_y1[Bv*Fv*Tv*Cv];
__device__ float g_y2[Bv*Fv*Tv*Cv];
__device__ float g_y3[Bv*Fv*Tv*Cv];
__device__ float g_l[NSPLIT*Bv*NHv*Fv*Tv];  // 1 MB (partial row sums)

__device__ __forceinline__ float gelu_f(float x) {
    return 0.5f * x * (1.0f + erff(x * 0.7071067811865476f));
}

// tanh-approx gelu (HW tanh.approx)
__device__ __forceinline__ float gelu_t(float x) {
    float u = 0.7978845608028654f * x * (1.0f + 0.044715f * x * x);
    float t;
    asm("tanh.approx.f32 %0, %1;" : "=f"(t) : "f"(u));
    return 0.5f * x * (1.0f + t);
}

// Guaranteed-MUFU exp2
__device__ __forceinline__ float ex2_approx(float x) {
    float y;
    asm("ex2.approx.f32 %0, %1;" : "=f"(y) : "f"(x));
    return y;
}

__device__ __forceinline__ uint32_t f2tf32(float f) {
    uint32_t u;
    asm("cvt.rna.tf32.f32 %0, %1;" : "=r"(u) : "f"(f));
    return u;
}

__device__ __forceinline__ uint32_t pack_bf16x2(float lo, float hi) {
    __nv_bfloat162 p = __floats2bfloat162_rn(lo, hi);   // x=lo, y=hi
    return *reinterpret_cast<uint32_t*>(&p);
}

__device__ __forceinline__ void mma_tf32(float c[4], const uint32_t a[4], const uint32_t b[2]) {
    asm volatile(
        "mma.sync.aligned.m16n8k8.row.col.f32.tf32.tf32.f32 "
        "{%0,%1,%2,%3},{%4,%5,%6,%7},{%8,%9},{%0,%1,%2,%3};"
        : "+f"(c[0]), "+f"(c[1]), "+f"(c[2]), "+f"(c[3])
        : "r"(a[0]), "r"(a[1]), "r"(a[2]), "r"(a[3]), "r"(b[0]), "r"(b[1]));
}

__device__ __forceinline__ void mma_bf16(float c[4], const uint32_t a[4], const uint32_t b[2]) {
    asm volatile(
        "mma.sync.aligned.m16n8k16.row.col.f32.bf16.bf16.f32 "
        "{%0,%1,%2,%3},{%4,%5,%6,%7},{%8,%9},{%0,%1,%2,%3};"
        : "+f"(c[0]), "+f"(c[1]), "+f"(c[2]), "+f"(c[3])
        : "r"(a[0]), "r"(a[1]), "r"(a[2]), "r"(a[3]), "r"(b[0]), "r"(b[1]));
}

// ---------------------------------------------------------------------------
// TCL v2 (unchanged from round 10 — 19.5us, validated)
// ---------------------------------------------------------------------------
#define XSTR 52

__global__ __launch_bounds__(128) void tcl_mma_kernel(
    const float* __restrict__ causal, const float* __restrict__ pastkv,
    float* __restrict__ qo, float* __restrict__ ko, float* __restrict__ vo,
    const float* __restrict__ wqc, const float* __restrict__ bqc,
    const float* __restrict__ wqp, const float* __restrict__ bqp,
    const float* __restrict__ wkc, const float* __restrict__ bkc,
    const float* __restrict__ wkp, const float* __restrict__ bkp,
    const float* __restrict__ wvc, const float* __restrict__ bvc,
    const float* __restrict__ wvp, const float* __restrict__ bvp)
{
    __shared__ uint32_t Xp[128*XSTR];
    __shared__ uint32_t Wcp[64*XSTR];
    __shared__ uint32_t Wpp[32*XSTR];
    __shared__ float bcs[C2v];
    __shared__ float bps[Cv];

    const int bid = blockIdx.x;
    const int stream = bid >> 3, tile = bid & 7;
    const float *x, *wconv, *bconv, *wproj, *bproj;
    float* out;
    if (stream < 32) {
        x = causal + (long)stream*32768; out = qo + (long)stream*32768;
        wconv = wqc; bconv = bqc; wproj = wqp; bproj = bqp;
    } else if (stream < 40) {
        int n = stream - 32;
        x = pastkv + (long)n*32768; out = ko + (long)n*32768;
        wconv = wkc; bconv = bkc; wproj = wkp; bproj = bkp;
    } else {
        int n = stream - 40;
        x = pastkv + (long)n*32768; out = vo + (long)n*32768;
        wconv = wvc; bconv = bvc; wproj = wvp; bproj = bvp;
    }

    const int tid = threadIdx.x;
    const int t0 = tile * 128;

    for (int i = tid; i < 64*48; i += 128) {
        int n = i / 48, kp = i % 48;
        int tap = kp >> 4, c = (kp & 15) * 2;
        Wcp[n*XSTR + kp] = pack_bf16x2(wconv[(n*Cv + c)*3 + tap],
                                       wconv[(n*Cv + c+1)*3 + tap]);
    }
    for (int i = tid; i < 32*32; i += 128) {
        int n = i >> 5, kp = i & 31;
        Wpp[n*XSTR + kp] = pack_bf16x2(wproj[n*C2v + 2*kp], wproj[n*C2v + 2*kp+1]);
    }
    if (tid < C2v) bcs[tid] = bconv[tid];
    if (tid < Cv)  bps[tid] = bproj[tid];

    for (int i = tid; i < 128*48; i += 128) {
        int r = i / 48, kp = i % 48;
        int tap = kp >> 4, c = (kp & 15) * 2;
        int t = t0 + r - 2 + tap;
        uint32_t val = 0u;
        if (t >= 0) {
            const float* src = x + (long)t*Cv + c;
            val = pack_bf16x2(src[0], src[1]);
        }
        Xp[r*XSTR + kp] = val;
    }
    __syncthreads();

    const int w  = tid >> 5, l = tid & 31;
    const int lq = l >> 2, lr = l & 3;
    const int r0 = w * 32;

    float Cc[2][8][4];
    #pragma unroll
    for (int mt = 0; mt < 2; mt++)
        #pragma unroll
        for (int nt = 0; nt < 8; nt++)
            #pragma unroll
            for (int e = 0; e < 4; e++) Cc[mt][nt][e] = 0.f;

    #pragma unroll
    for (int ks = 0; ks < 6; ks++) {
        uint32_t a[2][4];
        #pragma unroll
        for (int mt = 0; mt < 2; mt++) {
            int rr = r0 + mt*16;
            a[mt][0] = Xp[(rr+lq)*XSTR   + ks*8 + lr];
            a[mt][1] = Xp[(rr+lq+8)*XSTR + ks*8 + lr];
            a[mt][2] = Xp[(rr+lq)*XSTR   + ks*8 + lr + 4];
            a[mt][3] = Xp[(rr+lq+8)*XSTR + ks*8 + lr + 4];
        }
        #pragma unroll
        for (int nt = 0; nt < 8; nt++) {
            uint32_t bf[2];
            bf[0] = Wcp[(nt*8+lq)*XSTR + ks*8 + lr];
            bf[1] = Wcp[(nt*8+lq)*XSTR + ks*8 + lr + 4];
            mma_bf16(Cc[0][nt], a[0], bf);
            mma_bf16(Cc[1][nt], a[1], bf);
        }
    }

    uint32_t pa[2][4][4];
    #pragma unroll
    for (int ks2 = 0; ks2 < 4; ks2++) {
        float b0 = bcs[(2*ks2)*8   + 2*lr], b1 = bcs[(2*ks2)*8   + 2*lr + 1];
        float b2 = bcs[(2*ks2+1)*8 + 2*lr], b3 = bcs[(2*ks2+1)*8 + 2*lr + 1];
        #pragma unroll
        for (int mt = 0; mt < 2; mt++) {
            pa[mt][ks2][0] = pack_bf16x2(gelu_t(Cc[mt][2*ks2][0]+b0),   gelu_t(Cc[mt][2*ks2][1]+b1));
            pa[mt][ks2][1] = pack_bf16x2(gelu_t(Cc[mt][2*ks2][2]+b0),   gelu_t(Cc[mt][2*ks2][3]+b1));
            pa[mt][ks2][2] = pack_bf16x2(gelu_t(Cc[mt][2*ks2+1][0]+b2), gelu_t(Cc[mt][2*ks2+1][1]+b3));
            pa[mt][ks2][3] = pack_bf16x2(gelu_t(Cc[mt][2*ks2+1][2]+b2), gelu_t(Cc[mt][2*ks2+1][3]+b3));
        }
    }

    float Cp[2][4][4];
    #pragma unroll
    for (int mt = 0; mt < 2; mt++)
        #pragma unroll
        for (int nt = 0; nt < 4; nt++)
            #pragma unroll
            for (int e = 0; e < 4; e++) Cp[mt][nt][e] = 0.f;

    #pragma unroll
    for (int ks2 = 0; ks2 < 4; ks2++) {
        #pragma unroll
        for (int nt = 0; nt < 4; nt++) {
            uint32_t bf[2];
            bf[0] = Wpp[(nt*8+lq)*XSTR + ks2*8 + lr];
            bf[1] = Wpp[(nt*8+lq)*XSTR + ks2*8 + lr + 4];
            mma_bf16(Cp[0][nt], pa[0][ks2], bf);
            mma_bf16(Cp[1][nt], pa[1][ks2], bf);
        }
    }

    #pragma unroll
    for (int mt = 0; mt < 2; mt++) {
        #pragma unroll
        for (int nt = 0; nt < 4; nt++) {
            int col = nt*8 + 2*lr;
            float bo0 = bps[col], bo1 = bps[col+1];
            long row = t0 + r0 + mt*16 + lq;
            *(float2*)(out + row*Cv + col)     = make_float2(Cp[mt][nt][0]+bo0, Cp[mt][nt][1]+bo1);
            *(float2*)(out + (row+8)*Cv + col) = make_float2(Cp[mt][nt][2]+bo0, Cp[mt][nt][3]+bo1);
        }
    }
}

// ---------------------------------------------------------------------------
// Attention v5.2: round-13 body + __launch_bounds__(256,3) to force >=3
// blocks/SM (24 warps/SM) — attack latency exposure, not instruction count.
// ---------------------------------------------------------------------------
#define CH 256         // s range per block (= Sv/NSPLIT), staged once
#define KSTR 20        // Ks row stride (floats)
#define VSTR 24        // Vp pair-row stride (u32)
#define QSCALE 0.3606737602222409f   // 0.25 * log2(e)

__global__ __launch_bounds__(256, 3) void attn_mma_kernel(
    const float* __restrict__ q, const float* __restrict__ k,
    const float* __restrict__ v,
    float* __restrict__ y0, float* __restrict__ y1,
    float* __restrict__ y2, float* __restrict__ y3,
    float* __restrict__ lpart)
{
    __shared__ float    Ks[CH*KSTR];        // 20 KB
    __shared__ uint32_t Vp[(CH/2)*VSTR];    // 12 KB

    const int tid = threadIdx.x;
    const int w   = tid >> 5;
    const int l   = tid & 31;
    const int lq  = l >> 2;
    const int lr  = l & 3;
    const int b     = blockIdx.z;
    const int h     = blockIdx.y >> 2;
    const int split = blockIdx.y & 3;

    const int rowbase = blockIdx.x * 256 + w * 32;
    const int f  = rowbase >> 10;
    const int t0 = rowbase & 1023;
    const float* qbase = q + (((long)(b*Fv + f))*Tv + t0)*Cv + h*HDv;

    // Q fragments, prescaled by 0.25*log2(e) -> scores in log2 domain
    uint32_t qa[2][2][4];
    #pragma unroll
    for (int mt = 0; mt < 2; mt++)
        #pragma unroll
        for (int ks = 0; ks < 2; ks++) {
            int r0 = mt*16 + lq;
            int c0 = ks*8 + lr;
            qa[mt][ks][0] = f2tf32(qbase[(long)r0*Cv + c0]       * QSCALE);
            qa[mt][ks][1] = f2tf32(qbase[(long)(r0+8)*Cv + c0]   * QSCALE);
            qa[mt][ks][2] = f2tf32(qbase[(long)r0*Cv + c0+4]     * QSCALE);
            qa[mt][ks][3] = f2tf32(qbase[(long)(r0+8)*Cv + c0+4] * QSCALE);
        }

    float O[2][2][4];
    #pragma unroll
    for (int i = 0; i < 2; i++)
        #pragma unroll
        for (int j = 0; j < 2; j++)
            #pragma unroll
            for (int e = 0; e < 4; e++) O[i][j][e] = 0.f;
    float ls[4] = {0.f, 0.f, 0.f, 0.f};

    const int s0 = split * CH;
    const float* kb = k + ((long)b*Sv + s0)*Cv + h*HDv;
    const float* vb = v + ((long)b*Sv + s0)*Cv + h*HDv;

    // Stage once (no loop; SMEM read-only afterwards)
    for (int i = tid; i < CH*16; i += 256) {
        int s = i >> 4, d = i & 15;
        Ks[s*KSTR + d] = __uint_as_float(f2tf32(kb[(long)s*Cv + d]));
    }
    for (int i = tid; i < (CH/2)*16; i += 256) {
        int s2 = i >> 4, d = i & 15;
        Vp[s2*VSTR + d] = pack_bf16x2(vb[(long)(2*s2)*Cv + d],
                                      vb[(long)(2*s2+1)*Cv + d]);
    }
    __syncthreads();

    #pragma unroll 4
    for (int ntp = 0; ntp < CH/16; ntp++) {     // 16-s slices
        uint32_t pa[2][4];
        #pragma unroll
        for (int half = 0; half < 2; half++) {
            int snt = ntp*16 + half*8;
            uint32_t kf[2][2];
            #pragma unroll
            for (int ks = 0; ks < 2; ks++) {
                int dbase = ks*8 + lr;
                kf[ks][0] = __float_as_uint(Ks[(snt + lq)*KSTR + dbase]);
                kf[ks][1] = __float_as_uint(Ks[(snt + lq)*KSTR + dbase + 4]);
            }
            #pragma unroll
            for (int mt = 0; mt < 2; mt++) {
                float c[4] = {0.f, 0.f, 0.f, 0.f};
                mma_tf32(c, qa[mt][0], kf[0]);
                mma_tf32(c, qa[mt][1], kf[1]);
                float e0 = ex2_approx(fminf(c[0], 115.f));
                float e1 = ex2_approx(fminf(c[1], 115.f));
                float e2 = ex2_approx(fminf(c[2], 115.f));
                float e3 = ex2_approx(fminf(c[3], 115.f));
                ls[mt*2]   += e0 + e1;
                ls[mt*2+1] += e2 + e3;
                pa[mt][half*2 + 0] = pack_bf16x2(e0, e1);
                pa[mt][half*2 + 1] = pack_bf16x2(e2, e3);
            }
        }
        int s2base = ntp * 8;
        #pragma unroll
        for (int dn = 0; dn < 2; dn++) {
            uint32_t vf[2];
            vf[0] = Vp[(s2base + lr)*VSTR + dn*8 + lq];
            vf[1] = Vp[(s2base + lr + 4)*VSTR + dn*8 + lq];
            mma_bf16(O[0][dn], pa[0], vf);
            mma_bf16(O[1][dn], pa[1], vf);
        }
    }

    #pragma unroll
    for (int i = 0; i < 4; i++) {
        ls[i] += __shfl_xor_sync(0xffffffffu, ls[i], 1);
        ls[i] += __shfl_xor_sync(0xffffffffu, ls[i], 2);
    }

    float* ybuf = (split == 0) ? y0 : (split == 1) ? y1 : (split == 2) ? y2 : y3;
    float* yout = ybuf + (((long)(b*Fv + f))*Tv + t0)*Cv + h*HDv;
    #pragma unroll
    for (int mt = 0; mt < 2; mt++)
        #pragma unroll
        for (int dn = 0; dn < 2; dn++) {
            int d0 = dn*8 + 2*lr;
            int r0 = mt*16 + lq;
            *(float2*)(yout + (long)r0*Cv + d0)     = make_float2(O[mt][dn][0], O[mt][dn][1]);
            *(float2*)(yout + (long)(r0+8)*Cv + d0) = make_float2(O[mt][dn][2], O[mt][dn][3]);
        }

    if (lr == 0) {
        long lb = ((long)(split*Bv + b)*NHv + h)*(Fv*Tv) + rowbase;
        #pragma unroll
        for (int mt = 0; mt < 2; mt++) {
            lpart[lb + mt*16 + lq]     = ls[mt*2];
            lpart[lb + mt*16 + lq + 8] = ls[mt*2+1];
        }
    }
}

// ---------------------------------------------------------------------------
// Epilogue v2: 64 rows per block (8 rows/warp, looped) — 8x less redundant
// weight staging, more work per block to amortize latency. Grid = 512.
// ---------------------------------------------------------------------------
__global__ __launch_bounds__(256) void epi_kernel(
    const float* __restrict__ causal,
    const float* __restrict__ y0, const float* __restrict__ y1,
    const float* __restrict__ y2, const float* __restrict__ y3,
    const float* __restrict__ lpart,
    const float* __restrict__ wc, const float* __restrict__ lnw,
    const float* __restrict__ wfc, const float* __restrict__ wmp,
    float* __restrict__ out)
{
    __shared__ float wcs[32*32];
    __shared__ float wfcs[32*32];
    __shared__ float wmps[32*32];
    __shared__ float lns[32];
    __shared__ float stage[8][32];

    int tid = threadIdx.x;
    for (int i = tid; i < 1024; i += 256) {
        int a = i >> 5, bcol = i & 31;
        wcs[i]  = wc[bcol*32 + a];
        wfcs[i] = wfc[bcol*32 + a];
        wmps[i] = wmp[bcol*32 + a];
    }
    if (tid < 32) lns[tid] = lnw[tid];
    __syncthreads();

    int wid = tid >> 5, lane = tid & 31;
    int h = lane >> 4;
    const long LSTRIDE = (long)Bv*NHv*Fv*Tv;

    #pragma unroll 2
    for (int r = 0; r < 8; r++) {
        long row = (long)blockIdx.x * 64 + wid * 8 + r;   // < 32768
        int b  = (int)(row >> 12);
        int ft = (int)(row & 4095);

        long lidx = ((long)b*NHv + h)*(Fv*Tv) + ft;
        float lsum = lpart[lidx] + lpart[LSTRIDE + lidx]
                   + lpart[2*LSTRIDE + lidx] + lpart[3*LSTRIDE + lidx];
        float yc = (y0[row*32 + lane] + y1[row*32 + lane]
                  + y2[row*32 + lane] + y3[row*32 + lane]) / lsum;
        stage[wid][lane] = yc;
        __syncwarp();

        float o = causal[row*32 + lane];
        #pragma unroll
        for (int j = 0; j < 32; j++) o += stage[wid][j] * wcs[j*32 + lane];
        __syncwarp();

        float sum = o, sq = o*o;
        #pragma unroll
        for (int off = 16; off; off >>= 1) {
            sum += __shfl_xor_sync(0xffffffffu, sum, off);
            sq  += __shfl_xor_sync(0xffffffffu, sq, off);
        }
        float mu  = sum * (1.0f/32.0f);
        float var = sq  * (1.0f/32.0f) - mu*mu;
        float hn = (o - mu) * rsqrtf(var + 1e-5f) * lns[lane];

        stage[wid][lane] = hn;
        __syncwarp();
        float g = 0.f;
        #pragma unroll
        for (int j = 0; j < 32; j++) g += stage[wid][j] * wfcs[j*32 + lane];
        __syncwarp();
        g = gelu_f(g);
        stage[wid][lane] = g;
        __syncwarp();
        float mlp = 0.f;
        #pragma unroll
        for (int j = 0; j < 32; j++) mlp += stage[wid][j] * wmps[j*32 + lane];
        __syncwarp();

        out[row*32 + lane] = o + mlp;
    }
}

// ---------------------------------------------------------------------------
extern "C" void kernel_launch(void* const* d_in, const int* in_sizes, int n_in,
                              void* d_out, int out_size)
{
    const float* causal  = (const float*)d_in[0];
    const float* pastkv  = (const float*)d_in[1];
    const float* wq_conv = (const float*)d_in[2];
    const float* bq_conv = (const float*)d_in[3];
    const float* wq_proj = (const float*)d_in[4];
    const float* bq_proj = (const float*)d_in[5];
    const float* wk_conv = (const float*)d_in[6];
    const float* bk_conv = (const float*)d_in[7];
    const float* wk_proj = (const float*)d_in[8];
    const float* bk_proj = (const float*)d_in[9];
    const float* wv_conv = (const float*)d_in[10];
    const float* bv_conv = (const float*)d_in[11];
    const float* wv_proj = (const float*)d_in[12];
    const float* bv_proj = (const float*)d_in[13];
    const float* w_cproj = (const float*)d_in[14];
    const float* ln_w    = (const float*)d_in[15];
    const float* w_fc    = (const float*)d_in[16];
    const float* w_mlp   = (const float*)d_in[17];
    float* out = (float*)d_out;

    float *q, *k, *v, *y0, *y1, *y2, *y3, *lp;
    cudaGetSymbolAddress((void**)&q,  g_q);
    cudaGetSymbolAddress((void**)&k,  g_k);
    cudaGetSymbolAddress((void**)&v,  g_v);
    cudaGetSymbolAddress((void**)&y0, g_y0);
    cudaGetSymbolAddress((void**)&y1, g_y1);
    cudaGetSymbolAddress((void**)&y2, g_y2);
    cudaGetSymbolAddress((void**)&y3, g_y3);
    cudaGetSymbolAddress((void**)&lp, g_l);

    tcl_mma_kernel<<<384, 128>>>(causal, pastkv, q, k, v,
                                 wq_conv, bq_conv, wq_proj, bq_proj,
                                 wk_conv, bk_conv, wk_proj, bk_proj,
                                 wv_conv, bv_conv, wv_proj, bv_proj);

    // 256-row q tiles, S split in 4: grid (16, NHv*NSPLIT, Bv) = 1024 blocks
    attn_mma_kernel<<<dim3((Fv*Tv)/256, NHv*NSPLIT, Bv), 256>>>(q, k, v, y0, y1, y2, y3, lp);

    // 64 rows per block: 512 blocks
    epi_kernel<<<(Bv*Fv*Tv)/64, 256>>>(causal, y0, y1, y2, y3, lp,
                                       w_cproj, ln_w, w_fc, w_mlp, out);
}